// round 1
// baseline (speedup 1.0000x reference)
#include <cuda_runtime.h>
#include <cuda_bf16.h>
#include <math_constants.h>

#define B_      8
#define N_      8192
#define S_      2048
#define K_      16
#define DIN_    64
#define DOUT_   128
#define BN_EPS_ 1e-5f

// ---------------- scratch (static __device__ — no allocation allowed) ----------------
__device__ int   g_fps_idx[B_ * S_];
__device__ int   g_knn_idx[B_ * S_ * K_];
__device__ float g_h[B_ * N_ * DOUT_];   // 33.5 MB, post MLP+BN+ReLU features

// ============================================================================
// 1) Farthest point sampling — one CTA per batch, 1024 threads, 8 pts/thread.
//    Emits fps_idx AND writes new_coords (gathered coords) directly to output.
// ============================================================================
__global__ __launch_bounds__(1024, 1)
void fps_kernel(const float* __restrict__ coords, float* __restrict__ out_coords)
{
    const int b = blockIdx.x;
    const int t = threadIdx.x;
    const float* cb = coords + (size_t)b * N_ * 3;

    // register-resident coords + running min-distance
    float px[8], py[8], pz[8], pd[8];
#pragma unroll
    for (int j = 0; j < 8; j++) {
        int p = t + (j << 10);
        px[j] = cb[p * 3 + 0];
        py[j] = cb[p * 3 + 1];
        pz[j] = cb[p * 3 + 2];
        pd[j] = 1e10f;
    }

    __shared__ float s_val[32], s_x[32], s_y[32], s_z[32];
    __shared__ int   s_idx[32];
    __shared__ float s_c[3];
    __shared__ int   s_cur;

    // initial centroid = point 0 (owned by thread 0, j=0)
    if (t == 0) { s_c[0] = px[0]; s_c[1] = py[0]; s_c[2] = pz[0]; s_cur = 0; }
    __syncthreads();

    const unsigned FULL = 0xffffffffu;
    const int lane = t & 31;
    const int w    = t >> 5;

    for (int i = 0; i < S_; i++) {
        const float cx = s_c[0], cy = s_c[1], cz = s_c[2];
        const int cur = s_cur;
        if (t == 0) {
            g_fps_idx[b * S_ + i] = cur;
            float* oc = out_coords + ((size_t)b * S_ + i) * 3;
            oc[0] = cx; oc[1] = cy; oc[2] = cz;
        }

        // update distances + local argmax (first-index tie-break: ascending j, strict >)
        float m = -CUDART_INF_F;
        int   mi = t;
#pragma unroll
        for (int j = 0; j < 8; j++) {
            float dx = __fsub_rn(px[j], cx);
            float dy = __fsub_rn(py[j], cy);
            float dz = __fsub_rn(pz[j], cz);
            float dd = __fadd_rn(__fadd_rn(__fmul_rn(dx, dx), __fmul_rn(dy, dy)),
                                 __fmul_rn(dz, dz));
            pd[j] = fminf(pd[j], dd);
            if (pd[j] > m) { m = pd[j]; mi = t + (j << 10); }
        }
        // recover candidate coords (register select, unrolled)
        float mx = px[0], my = py[0], mz = pz[0];
        int js = mi >> 10;
#pragma unroll
        for (int j = 1; j < 8; j++)
            if (js == j) { mx = px[j]; my = py[j]; mz = pz[j]; }

        // warp reduce: (val, idx, x, y, z); tie -> smaller index
#pragma unroll
        for (int off = 16; off > 0; off >>= 1) {
            float om = __shfl_down_sync(FULL, m,  off);
            int   oi = __shfl_down_sync(FULL, mi, off);
            float ox = __shfl_down_sync(FULL, mx, off);
            float oy = __shfl_down_sync(FULL, my, off);
            float oz = __shfl_down_sync(FULL, mz, off);
            if (om > m || (om == m && oi < mi)) { m = om; mi = oi; mx = ox; my = oy; mz = oz; }
        }
        if (lane == 0) { s_val[w] = m; s_idx[w] = mi; s_x[w] = mx; s_y[w] = my; s_z[w] = mz; }
        __syncthreads();

        if (t < 32) {
            m = s_val[t]; mi = s_idx[t]; mx = s_x[t]; my = s_y[t]; mz = s_z[t];
#pragma unroll
            for (int off = 16; off > 0; off >>= 1) {
                float om = __shfl_down_sync(FULL, m,  off);
                int   oi = __shfl_down_sync(FULL, mi, off);
                float ox = __shfl_down_sync(FULL, mx, off);
                float oy = __shfl_down_sync(FULL, my, off);
                float oz = __shfl_down_sync(FULL, mz, off);
                if (om > m || (om == m && oi < mi)) { m = om; mi = oi; mx = ox; my = oy; mz = oz; }
            }
            if (t == 0) { s_c[0] = mx; s_c[1] = my; s_c[2] = mz; s_cur = mi; }
        }
        __syncthreads();
    }
}

// ============================================================================
// 2) KNN: for each sampled point, K=16 smallest (d, idx) lexicographic
//    (matches jax.lax.top_k(-d) tie-breaking). 1 thread per query, smem tiles.
// ============================================================================
__global__ __launch_bounds__(128)
void knn_kernel(const float* __restrict__ coords)
{
    const int b = blockIdx.y;
    const int s = blockIdx.x * 128 + threadIdx.x;
    const float* cb = coords + (size_t)b * N_ * 3;

    const int qi = g_fps_idx[b * S_ + s];
    const float qx = cb[qi * 3 + 0];
    const float qy = cb[qi * 3 + 1];
    const float qz = cb[qi * 3 + 2];

    __shared__ float tile[2048 * 3];

    float dk[K_];
    int   ik[K_];
#pragma unroll
    for (int j = 0; j < K_; j++) { dk[j] = CUDART_INF_F; ik[j] = 0; }

    for (int t0 = 0; t0 < N_; t0 += 2048) {
        __syncthreads();
        for (int v = threadIdx.x; v < 2048 * 3; v += 128)
            tile[v] = cb[t0 * 3 + v];
        __syncthreads();

        for (int p = 0; p < 2048; p++) {
            float dx = __fsub_rn(qx, tile[p * 3 + 0]);
            float dy = __fsub_rn(qy, tile[p * 3 + 1]);
            float dz = __fsub_rn(qz, tile[p * 3 + 2]);
            float dd = __fadd_rn(__fadd_rn(__fmul_rn(dx, dx), __fmul_rn(dy, dy)),
                                 __fmul_rn(dz, dz));
            if (dd < dk[K_ - 1]) {            // strict <: keep earlier index on ties
                float vd = dd; int vi = t0 + p;
#pragma unroll
                for (int j = 0; j < K_; j++) {
                    if (vd < dk[j]) {
                        float td = dk[j]; int ti = ik[j];
                        dk[j] = vd; ik[j] = vi;
                        vd = td; vi = ti;
                    }
                }
            }
        }
    }

    int* out = &g_knn_idx[((size_t)b * S_ + s) * K_];
#pragma unroll
    for (int j = 0; j < K_; j++) out[j] = ik[j];
}

// ============================================================================
// 3) Pointwise MLP (64->128) + BN(eval) + ReLU on ALL points -> g_h.
//    32 points/block, 256 threads: o = tid%128, each thread 16 points.
//    W row in registers, features via float4 smem broadcast -> FMA-bound.
// ============================================================================
__global__ __launch_bounds__(256)
void mlp_kernel(const float* __restrict__ features,
                const float* __restrict__ W,
                const float* __restrict__ bias,
                const float* __restrict__ gamma,
                const float* __restrict__ beta,
                const float* __restrict__ rmean,
                const float* __restrict__ rvar)
{
    const int pt0  = blockIdx.x * 32;           // flat point index in [0, B*N)
    const int o    = threadIdx.x & 127;
    const int half = threadIdx.x >> 7;

    __shared__ float sW[DOUT_ * DIN_];          // 32 KB
    __shared__ float sF[32 * DIN_];             // 8 KB

    for (int v = threadIdx.x; v < DOUT_ * DIN_; v += 256) sW[v] = W[v];
    for (int v = threadIdx.x; v < 32 * DIN_;   v += 256) sF[v] = features[(size_t)pt0 * DIN_ + v];
    __syncthreads();

    float w[DIN_];
#pragma unroll
    for (int d = 0; d < DIN_; d++) w[d] = sW[o * DIN_ + d];

    const float bo = bias[o];
    const float mn = rmean[o];
    const float sc = gamma[o] * rsqrtf(rvar[o] + BN_EPS_);
    const float bt = beta[o];

    for (int p = half * 16; p < half * 16 + 16; p++) {
        float acc = 0.0f;
#pragma unroll
        for (int d = 0; d < DIN_; d += 4) {
            float4 f = *(const float4*)&sF[p * DIN_ + d];
            acc = fmaf(w[d + 0], f.x, acc);
            acc = fmaf(w[d + 1], f.y, acc);
            acc = fmaf(w[d + 2], f.z, acc);
            acc = fmaf(w[d + 3], f.w, acc);
        }
        float lin = acc + bo;
        float val = (lin - mn) * sc + bt;
        g_h[((size_t)pt0 + p) * DOUT_ + o] = fmaxf(val, 0.0f);
    }
}

// ============================================================================
// 4) Gather K neighbors' features + max-pool. warp = one query row,
//    lane = one float4 column (32 * 4 = 128 outputs).
// ============================================================================
__global__ __launch_bounds__(256)
void pool_kernel(float* __restrict__ out_feat)
{
    const int b   = blockIdx.y;
    const int s   = blockIdx.x * 8 + (threadIdx.x >> 5);
    const int col = threadIdx.x & 31;

    const int* kid = &g_knn_idx[((size_t)b * S_ + s) * K_];

    float4 acc = make_float4(-CUDART_INF_F, -CUDART_INF_F, -CUDART_INF_F, -CUDART_INF_F);
#pragma unroll
    for (int k = 0; k < K_; k++) {
        const int id = kid[k];
        const float4 v = *(const float4*)&g_h[((size_t)b * N_ + id) * DOUT_ + col * 4];
        acc.x = fmaxf(acc.x, v.x);
        acc.y = fmaxf(acc.y, v.y);
        acc.z = fmaxf(acc.z, v.z);
        acc.w = fmaxf(acc.w, v.w);
    }
    *(float4*)&out_feat[((size_t)b * S_ + s) * DOUT_ + col * 4] = acc;
}

// ============================================================================
extern "C" void kernel_launch(void* const* d_in, const int* in_sizes, int n_in,
                              void* d_out, int out_size)
{
    const float* coords   = (const float*)d_in[0];
    const float* features = (const float*)d_in[1];
    const float* W        = (const float*)d_in[2];
    const float* bias     = (const float*)d_in[3];
    const float* gamma    = (const float*)d_in[4];
    const float* beta     = (const float*)d_in[5];
    const float* rmean    = (const float*)d_in[6];
    const float* rvar     = (const float*)d_in[7];

    float* out        = (float*)d_out;
    float* out_coords = out;                       // [B, S, 3]
    float* out_feat   = out + (size_t)B_ * S_ * 3; // [B, S, 128]

    // FPS (long pole) first; MLP independent; KNN needs fps_idx; pool needs both.
    fps_kernel<<<B_, 1024>>>(coords, out_coords);
    mlp_kernel<<<(B_ * N_) / 32, 256>>>(features, W, bias, gamma, beta, rmean, rvar);
    knn_kernel<<<dim3(S_ / 128, B_), 128>>>(coords);
    pool_kernel<<<dim3(S_ / 8, B_), 256>>>(out_feat);
}

// round 2
// speedup vs baseline: 1.8203x; 1.8203x over previous
#include <cuda_runtime.h>
#include <cuda_bf16.h>
#include <math_constants.h>

#define B_      8
#define N_      8192
#define S_      2048
#define K_      16
#define DIN_    64
#define DOUT_   128
#define BN_EPS_ 1e-5f

// ---------------- scratch (static __device__ — no allocation allowed) ----------------
__device__ int   g_fps_idx[B_ * S_];
__device__ int   g_knn_idx[B_ * S_ * K_];
__device__ float g_h[B_ * N_ * DOUT_];   // 33.5 MB, post MLP+BN+ReLU features

// ---------------- packed f32x2 helpers (exact IEEE per lane) ----------------
__device__ __forceinline__ unsigned long long pack2(float lo, float hi) {
    unsigned long long r;
    asm("mov.b64 %0, {%1, %2};" : "=l"(r) : "f"(lo), "f"(hi));
    return r;
}
__device__ __forceinline__ void unpack2(unsigned long long v, float& lo, float& hi) {
    asm("mov.b64 {%0, %1}, %2;" : "=f"(lo), "=f"(hi) : "l"(v));
}
__device__ __forceinline__ unsigned long long add2(unsigned long long a, unsigned long long b) {
    unsigned long long r;
    asm("add.rn.f32x2 %0, %1, %2;" : "=l"(r) : "l"(a), "l"(b));
    return r;
}
__device__ __forceinline__ unsigned long long mul2(unsigned long long a, unsigned long long b) {
    unsigned long long r;
    asm("mul.rn.f32x2 %0, %1, %2;" : "=l"(r) : "l"(a), "l"(b));
    return r;
}

// ============================================================================
// 1) Farthest point sampling — one CTA per batch, 1024 threads, 8 pts/thread.
//    Coords register-resident (packed f32x2 pairs) + mirrored in dynamic smem
//    so the reduction only carries (max_bits, index); winner coords fetched
//    from smem by thread 0. Distance math = exact IEEE sub/mul/add ordering
//    ((dx^2+dy^2)+dz^2), matching the reference bit-for-bit.
// ============================================================================
extern __shared__ float s_dyn[];   // s_cx[N_], s_cy[N_], s_cz[N_]  (96 KB)

__global__ __launch_bounds__(1024, 1)
void fps_kernel(const float* __restrict__ coords, float* __restrict__ out_coords)
{
    float* s_cx = s_dyn;
    float* s_cy = s_dyn + N_;
    float* s_cz = s_dyn + 2 * N_;

    __shared__ unsigned s_val[32];
    __shared__ unsigned s_idx[32];
    __shared__ float    s_c[3];
    __shared__ unsigned s_cur;

    const int b = blockIdx.x;
    const int t = threadIdx.x;
    const float* cb = coords + (size_t)b * N_ * 3;

    unsigned long long pxx[4], pyy[4], pzz[4];
    float pd[8];

    {
        float lx[8], ly[8], lz[8];
#pragma unroll
        for (int j = 0; j < 8; j++) {
            int p = t + (j << 10);
            lx[j] = cb[p * 3 + 0];
            ly[j] = cb[p * 3 + 1];
            lz[j] = cb[p * 3 + 2];
            s_cx[p] = lx[j]; s_cy[p] = ly[j]; s_cz[p] = lz[j];
            pd[j] = 1e10f;
        }
#pragma unroll
        for (int j = 0; j < 4; j++) {
            pxx[j] = pack2(lx[2 * j], lx[2 * j + 1]);
            pyy[j] = pack2(ly[2 * j], ly[2 * j + 1]);
            pzz[j] = pack2(lz[2 * j], lz[2 * j + 1]);
        }
    }
    __syncthreads();
    if (t == 0) { s_c[0] = s_cx[0]; s_c[1] = s_cy[0]; s_c[2] = s_cz[0]; s_cur = 0u; }
    __syncthreads();

    const unsigned FULL = 0xffffffffu;

    for (int i = 0; i < S_; i++) {
        const float cx = s_c[0], cy = s_c[1], cz = s_c[2];
        const unsigned cur = s_cur;
        if (t == 0) {
            g_fps_idx[b * S_ + i] = (int)cur;
            float* oc = out_coords + ((size_t)b * S_ + i) * 3;
            oc[0] = cx; oc[1] = cy; oc[2] = cz;
        }

        const unsigned long long ncx = pack2(-cx, -cx);
        const unsigned long long ncy = pack2(-cy, -cy);
        const unsigned long long ncz = pack2(-cz, -cz);

#pragma unroll
        for (int j = 0; j < 4; j++) {
            unsigned long long dx = add2(pxx[j], ncx);     // px - cx (exact)
            unsigned long long dy = add2(pyy[j], ncy);
            unsigned long long dz = add2(pzz[j], ncz);
            unsigned long long dd = add2(add2(mul2(dx, dx), mul2(dy, dy)), mul2(dz, dz));
            float d0, d1;
            unpack2(dd, d0, d1);
            pd[2 * j]     = fminf(pd[2 * j],     d0);
            pd[2 * j + 1] = fminf(pd[2 * j + 1], d1);
        }

        // thread-local max (value) via tree, then first-match index (ascending
        // register j == ascending global index for this thread)
        float m01 = fmaxf(pd[0], pd[1]);
        float m23 = fmaxf(pd[2], pd[3]);
        float m45 = fmaxf(pd[4], pd[5]);
        float m67 = fmaxf(pd[6], pd[7]);
        float m = fmaxf(fmaxf(m01, m23), fmaxf(m45, m67));

        int bj = 7;
#pragma unroll
        for (int jj = 6; jj >= 0; jj--)
            if (pd[jj] == m) bj = jj;
        unsigned mi = (unsigned)(t + (bj << 10));

        // warp argmax: distances >= 0 so float bits are order-isomorphic to u32
        unsigned mb = __float_as_uint(m);
        unsigned wm = __reduce_max_sync(FULL, mb);
        unsigned cand = (mb == wm) ? mi : 0xffffffffu;
        unsigned wmi = __reduce_min_sync(FULL, cand);
        if ((t & 31) == 0) { s_val[t >> 5] = wm; s_idx[t >> 5] = wmi; }
        __syncthreads();

        if (t < 32) {
            unsigned v  = s_val[t];
            unsigned ix = s_idx[t];
            unsigned wm2 = __reduce_max_sync(FULL, v);
            unsigned c2  = (v == wm2) ? ix : 0xffffffffu;
            unsigned g   = __reduce_min_sync(FULL, c2);
            if (t == 0) {
                s_cur = g;
                s_c[0] = s_cx[g]; s_c[1] = s_cy[g]; s_c[2] = s_cz[g];
            }
        }
        __syncthreads();
    }
}

// ============================================================================
// 2) KNN: K=16 smallest (d, idx) lexicographic (matches top_k(-d)).
//    1 thread per query, float4-padded smem tiles (1 LDS.128 per point).
// ============================================================================
__global__ __launch_bounds__(128)
void knn_kernel(const float* __restrict__ coords)
{
    const int b = blockIdx.y;
    const int s = blockIdx.x * 128 + threadIdx.x;
    const float* cb = coords + (size_t)b * N_ * 3;

    const int qi = g_fps_idx[b * S_ + s];
    const float qx = cb[qi * 3 + 0];
    const float qy = cb[qi * 3 + 1];
    const float qz = cb[qi * 3 + 2];

    __shared__ float4 tile[2048];     // 32 KB, padded xyz

    float dk[K_];
    int   ik[K_];
#pragma unroll
    for (int j = 0; j < K_; j++) { dk[j] = CUDART_INF_F; ik[j] = 0; }

    for (int t0 = 0; t0 < N_; t0 += 2048) {
        __syncthreads();
        for (int v = threadIdx.x; v < 2048; v += 128) {
            int p = t0 + v;
            tile[v] = make_float4(cb[p * 3 + 0], cb[p * 3 + 1], cb[p * 3 + 2], 0.0f);
        }
        __syncthreads();

#pragma unroll 4
        for (int p = 0; p < 2048; p++) {
            float4 c = tile[p];
            float dx = __fsub_rn(qx, c.x);
            float dy = __fsub_rn(qy, c.y);
            float dz = __fsub_rn(qz, c.z);
            float dd = __fadd_rn(__fadd_rn(__fmul_rn(dx, dx), __fmul_rn(dy, dy)),
                                 __fmul_rn(dz, dz));
            if (dd < dk[K_ - 1]) {            // strict <: keep earlier index on ties
                float vd = dd; int vi = t0 + p;
#pragma unroll
                for (int j = 0; j < K_; j++) {
                    if (vd < dk[j]) {
                        float td = dk[j]; int ti = ik[j];
                        dk[j] = vd; ik[j] = vi;
                        vd = td; vi = ti;
                    }
                }
            }
        }
    }

    int* out = &g_knn_idx[((size_t)b * S_ + s) * K_];
#pragma unroll
    for (int j = 0; j < K_; j++) out[j] = ik[j];
}

// ============================================================================
// 3) Pointwise MLP (64->128) + BN(eval) + ReLU on ALL points -> g_h.
// ============================================================================
__global__ __launch_bounds__(256)
void mlp_kernel(const float* __restrict__ features,
                const float* __restrict__ W,
                const float* __restrict__ bias,
                const float* __restrict__ gamma,
                const float* __restrict__ beta,
                const float* __restrict__ rmean,
                const float* __restrict__ rvar)
{
    const int pt0  = blockIdx.x * 32;
    const int o    = threadIdx.x & 127;
    const int half = threadIdx.x >> 7;

    __shared__ float sW[DOUT_ * DIN_];          // 32 KB
    __shared__ float sF[32 * DIN_];             // 8 KB

    for (int v = threadIdx.x; v < DOUT_ * DIN_; v += 256) sW[v] = W[v];
    for (int v = threadIdx.x; v < 32 * DIN_;   v += 256) sF[v] = features[(size_t)pt0 * DIN_ + v];
    __syncthreads();

    float w[DIN_];
#pragma unroll
    for (int d = 0; d < DIN_; d++) w[d] = sW[o * DIN_ + d];

    const float bo = bias[o];
    const float mn = rmean[o];
    const float sc = gamma[o] * rsqrtf(rvar[o] + BN_EPS_);
    const float bt = beta[o];

    for (int p = half * 16; p < half * 16 + 16; p++) {
        float acc = 0.0f;
#pragma unroll
        for (int d = 0; d < DIN_; d += 4) {
            float4 f = *(const float4*)&sF[p * DIN_ + d];
            acc = fmaf(w[d + 0], f.x, acc);
            acc = fmaf(w[d + 1], f.y, acc);
            acc = fmaf(w[d + 2], f.z, acc);
            acc = fmaf(w[d + 3], f.w, acc);
        }
        float lin = acc + bo;
        float val = (lin - mn) * sc + bt;
        g_h[((size_t)pt0 + p) * DOUT_ + o] = fmaxf(val, 0.0f);
    }
}

// ============================================================================
// 4) Gather K neighbors' features + max-pool.
// ============================================================================
__global__ __launch_bounds__(256)
void pool_kernel(float* __restrict__ out_feat)
{
    const int b   = blockIdx.y;
    const int s   = blockIdx.x * 8 + (threadIdx.x >> 5);
    const int col = threadIdx.x & 31;

    const int* kid = &g_knn_idx[((size_t)b * S_ + s) * K_];

    float4 acc = make_float4(-CUDART_INF_F, -CUDART_INF_F, -CUDART_INF_F, -CUDART_INF_F);
#pragma unroll
    for (int k = 0; k < K_; k++) {
        const int id = kid[k];
        const float4 v = *(const float4*)&g_h[((size_t)b * N_ + id) * DOUT_ + col * 4];
        acc.x = fmaxf(acc.x, v.x);
        acc.y = fmaxf(acc.y, v.y);
        acc.z = fmaxf(acc.z, v.z);
        acc.w = fmaxf(acc.w, v.w);
    }
    *(float4*)&out_feat[((size_t)b * S_ + s) * DOUT_ + col * 4] = acc;
}

// ============================================================================
extern "C" void kernel_launch(void* const* d_in, const int* in_sizes, int n_in,
                              void* d_out, int out_size)
{
    const float* coords   = (const float*)d_in[0];
    const float* features = (const float*)d_in[1];
    const float* W        = (const float*)d_in[2];
    const float* bias     = (const float*)d_in[3];
    const float* gamma    = (const float*)d_in[4];
    const float* beta     = (const float*)d_in[5];
    const float* rmean    = (const float*)d_in[6];
    const float* rvar     = (const float*)d_in[7];

    float* out        = (float*)d_out;
    float* out_coords = out;                       // [B, S, 3]
    float* out_feat   = out + (size_t)B_ * S_ * 3; // [B, S, 128]

    static bool attr_done = false;
    if (!attr_done) {
        cudaFuncSetAttribute(fps_kernel, cudaFuncAttributeMaxDynamicSharedMemorySize,
                             3 * N_ * (int)sizeof(float));
        attr_done = true;
    }

    fps_kernel<<<B_, 1024, 3 * N_ * sizeof(float)>>>(coords, out_coords);
    mlp_kernel<<<(B_ * N_) / 32, 256>>>(features, W, bias, gamma, beta, rmean, rvar);
    knn_kernel<<<dim3(S_ / 128, B_), 128>>>(coords);
    pool_kernel<<<dim3(S_ / 8, B_), 256>>>(out_feat);
}

// round 3
// speedup vs baseline: 2.1237x; 1.1667x over previous
#include <cuda_runtime.h>
#include <cuda_bf16.h>
#include <math_constants.h>

#define B_      8
#define N_      8192
#define S_      2048
#define K_      16
#define DIN_    64
#define DOUT_   128
#define BN_EPS_ 1e-5f

// ---------------- scratch (static __device__ — no allocation allowed) ----------------
__device__ int   g_fps_idx[B_ * S_];
__device__ int   g_knn_idx[B_ * S_ * K_];
__device__ float g_h[B_ * N_ * DOUT_];   // 33.5 MB, post MLP+BN+ReLU features

// ---------------- packed f32x2 helpers (exact IEEE per lane) ----------------
__device__ __forceinline__ unsigned long long pack2(float lo, float hi) {
    unsigned long long r;
    asm("mov.b64 %0, {%1, %2};" : "=l"(r) : "f"(lo), "f"(hi));
    return r;
}
__device__ __forceinline__ void unpack2(unsigned long long v, float& lo, float& hi) {
    asm("mov.b64 {%0, %1}, %2;" : "=f"(lo), "=f"(hi) : "l"(v));
}
__device__ __forceinline__ unsigned long long add2(unsigned long long a, unsigned long long b) {
    unsigned long long r;
    asm("add.rn.f32x2 %0, %1, %2;" : "=l"(r) : "l"(a), "l"(b));
    return r;
}
__device__ __forceinline__ unsigned long long mul2(unsigned long long a, unsigned long long b) {
    unsigned long long r;
    asm("mul.rn.f32x2 %0, %1, %2;" : "=l"(r) : "l"(a), "l"(b));
    return r;
}

// ============================================================================
// 1) Farthest point sampling — one CTA per batch, 1024 threads, 8 pts/thread
//    (contiguous: thread t owns points 8t..8t+7 so lexicographic tie-break ==
//    global index order). ONE barrier per iteration:
//      warp redux -> lane0 writes (val,idx) to double-buffered smem -> BAR ->
//      every warp redundantly reduces the 32 warp results -> g known by all.
//    Winner coords come from a float4 smem table with a single broadcast LDS.128.
//    Distance math: exact IEEE a+(-b), mul, ((x+y)+z) — bit-identical to ref.
// ============================================================================
extern __shared__ float4 s_pts[];   // [N_] = 128 KB

__global__ __launch_bounds__(1024, 1)
void fps_kernel(const float* __restrict__ coords, float* __restrict__ out_coords)
{
    __shared__ unsigned s_val[2][32];
    __shared__ unsigned s_idx[2][32];

    const int b = blockIdx.x;
    const int t = threadIdx.x;
    const int lane = t & 31;
    const int w    = t >> 5;
    const float* cb = coords + (size_t)b * N_ * 3;

    unsigned long long pxx[4], pyy[4], pzz[4];
    float pd[8];

    {
        // thread t loads 24 contiguous floats = points 8t..8t+7
        float f[24];
        const float4* src = (const float4*)(cb + t * 24);
#pragma unroll
        for (int q = 0; q < 6; q++) {
            float4 v = src[q];
            f[q * 4 + 0] = v.x; f[q * 4 + 1] = v.y; f[q * 4 + 2] = v.z; f[q * 4 + 3] = v.w;
        }
#pragma unroll
        for (int j = 0; j < 8; j++) {
            s_pts[t * 8 + j] = make_float4(f[3 * j], f[3 * j + 1], f[3 * j + 2], 0.0f);
            pd[j] = 1e10f;
        }
#pragma unroll
        for (int jj = 0; jj < 4; jj++) {
            pxx[jj] = pack2(f[6 * jj + 0], f[6 * jj + 3]);
            pyy[jj] = pack2(f[6 * jj + 1], f[6 * jj + 4]);
            pzz[jj] = pack2(f[6 * jj + 2], f[6 * jj + 5]);
        }
    }
    __syncthreads();

    const unsigned FULL = 0xffffffffu;
    unsigned g = 0u;                 // current winner (same value in every thread)
    float4   c = s_pts[0];           // its coords
    int buf = 0;

    for (int i = 0; i < S_; i++) {
        if (t == 0) {
            g_fps_idx[b * S_ + i] = (int)g;
            float* oc = out_coords + ((size_t)b * S_ + i) * 3;
            oc[0] = c.x; oc[1] = c.y; oc[2] = c.z;
        }

        const unsigned long long ncx = pack2(-c.x, -c.x);
        const unsigned long long ncy = pack2(-c.y, -c.y);
        const unsigned long long ncz = pack2(-c.z, -c.z);

#pragma unroll
        for (int jj = 0; jj < 4; jj++) {
            unsigned long long dx = add2(pxx[jj], ncx);     // p - c, exact
            unsigned long long dy = add2(pyy[jj], ncy);
            unsigned long long dz = add2(pzz[jj], ncz);
            unsigned long long dd = add2(add2(mul2(dx, dx), mul2(dy, dy)), mul2(dz, dz));
            float d0, d1;
            unpack2(dd, d0, d1);
            pd[2 * jj]     = fminf(pd[2 * jj],     d0);
            pd[2 * jj + 1] = fminf(pd[2 * jj + 1], d1);
        }

        // thread-local max, then first-match (smallest j == smallest global idx)
        float m = fmaxf(fmaxf(fmaxf(pd[0], pd[1]), fmaxf(pd[2], pd[3])),
                        fmaxf(fmaxf(pd[4], pd[5]), fmaxf(pd[6], pd[7])));
        int bj = 7;
#pragma unroll
        for (int jj = 6; jj >= 0; jj--)
            if (pd[jj] == m) bj = jj;
        unsigned mi = (unsigned)(t * 8 + bj);

        // warp argmax (distances >= 0 -> float bits order-isomorphic to u32)
        unsigned mb = __float_as_uint(m);
        unsigned wm = __reduce_max_sync(FULL, mb);
        unsigned cand = (mb == wm) ? mi : 0xffffffffu;
        unsigned wmi = __reduce_min_sync(FULL, cand);
        if (lane == 0) { s_val[buf][w] = wm; s_idx[buf][w] = wmi; }
        __syncthreads();

        // every warp reduces the 32 per-warp results itself (no 2nd barrier)
        unsigned v  = s_val[buf][lane];
        unsigned ix = s_idx[buf][lane];
        unsigned gm = __reduce_max_sync(FULL, v);
        unsigned c2 = (v == gm) ? ix : 0xffffffffu;
        g = __reduce_min_sync(FULL, c2);
        c = s_pts[g];                 // broadcast LDS.128
        buf ^= 1;
    }
}

// ============================================================================
// 2) KNN: K=16 smallest (d, idx) lexicographic (matches top_k(-d)).
//    1 thread per query, float4-padded smem tiles (1 LDS.128 per point).
// ============================================================================
__global__ __launch_bounds__(128)
void knn_kernel(const float* __restrict__ coords)
{
    const int b = blockIdx.y;
    const int s = blockIdx.x * 128 + threadIdx.x;
    const float* cb = coords + (size_t)b * N_ * 3;

    const int qi = g_fps_idx[b * S_ + s];
    const float qx = cb[qi * 3 + 0];
    const float qy = cb[qi * 3 + 1];
    const float qz = cb[qi * 3 + 2];

    __shared__ float4 tile[2048];     // 32 KB, padded xyz

    float dk[K_];
    int   ik[K_];
#pragma unroll
    for (int j = 0; j < K_; j++) { dk[j] = CUDART_INF_F; ik[j] = 0; }

    for (int t0 = 0; t0 < N_; t0 += 2048) {
        __syncthreads();
        for (int v = threadIdx.x; v < 2048; v += 128) {
            int p = t0 + v;
            tile[v] = make_float4(cb[p * 3 + 0], cb[p * 3 + 1], cb[p * 3 + 2], 0.0f);
        }
        __syncthreads();

#pragma unroll 8
        for (int p = 0; p < 2048; p++) {
            float4 cc = tile[p];
            float dx = __fsub_rn(qx, cc.x);
            float dy = __fsub_rn(qy, cc.y);
            float dz = __fsub_rn(qz, cc.z);
            float dd = __fadd_rn(__fadd_rn(__fmul_rn(dx, dx), __fmul_rn(dy, dy)),
                                 __fmul_rn(dz, dz));
            if (dd < dk[K_ - 1]) {            // strict <: keep earlier index on ties
                float vd = dd; int vi = t0 + p;
#pragma unroll
                for (int j = 0; j < K_; j++) {
                    if (vd < dk[j]) {
                        float td = dk[j]; int ti = ik[j];
                        dk[j] = vd; ik[j] = vi;
                        vd = td; vi = ti;
                    }
                }
            }
        }
    }

    int* out = &g_knn_idx[((size_t)b * S_ + s) * K_];
#pragma unroll
    for (int j = 0; j < K_; j++) out[j] = ik[j];
}

// ============================================================================
// 3) Pointwise MLP (64->128) + BN(eval) + ReLU on ALL points -> g_h.
// ============================================================================
__global__ __launch_bounds__(256)
void mlp_kernel(const float* __restrict__ features,
                const float* __restrict__ W,
                const float* __restrict__ bias,
                const float* __restrict__ gamma,
                const float* __restrict__ beta,
                const float* __restrict__ rmean,
                const float* __restrict__ rvar)
{
    const int pt0  = blockIdx.x * 32;
    const int o    = threadIdx.x & 127;
    const int half = threadIdx.x >> 7;

    __shared__ float sW[DOUT_ * DIN_];          // 32 KB
    __shared__ float sF[32 * DIN_];             // 8 KB

    for (int v = threadIdx.x; v < DOUT_ * DIN_; v += 256) sW[v] = W[v];
    for (int v = threadIdx.x; v < 32 * DIN_;   v += 256) sF[v] = features[(size_t)pt0 * DIN_ + v];
    __syncthreads();

    float w[DIN_];
#pragma unroll
    for (int d = 0; d < DIN_; d++) w[d] = sW[o * DIN_ + d];

    const float bo = bias[o];
    const float mn = rmean[o];
    const float sc = gamma[o] * rsqrtf(rvar[o] + BN_EPS_);
    const float bt = beta[o];

    for (int p = half * 16; p < half * 16 + 16; p++) {
        float acc = 0.0f;
#pragma unroll
        for (int d = 0; d < DIN_; d += 4) {
            float4 f = *(const float4*)&sF[p * DIN_ + d];
            acc = fmaf(w[d + 0], f.x, acc);
            acc = fmaf(w[d + 1], f.y, acc);
            acc = fmaf(w[d + 2], f.z, acc);
            acc = fmaf(w[d + 3], f.w, acc);
        }
        float lin = acc + bo;
        float val = (lin - mn) * sc + bt;
        g_h[((size_t)pt0 + p) * DOUT_ + o] = fmaxf(val, 0.0f);
    }
}

// ============================================================================
// 4) Gather K neighbors' features + max-pool.
// ============================================================================
__global__ __launch_bounds__(256)
void pool_kernel(float* __restrict__ out_feat)
{
    const int b   = blockIdx.y;
    const int s   = blockIdx.x * 8 + (threadIdx.x >> 5);
    const int col = threadIdx.x & 31;

    const int* kid = &g_knn_idx[((size_t)b * S_ + s) * K_];

    float4 acc = make_float4(-CUDART_INF_F, -CUDART_INF_F, -CUDART_INF_F, -CUDART_INF_F);
#pragma unroll
    for (int k = 0; k < K_; k++) {
        const int id = kid[k];
        const float4 v = *(const float4*)&g_h[((size_t)b * N_ + id) * DOUT_ + col * 4];
        acc.x = fmaxf(acc.x, v.x);
        acc.y = fmaxf(acc.y, v.y);
        acc.z = fmaxf(acc.z, v.z);
        acc.w = fmaxf(acc.w, v.w);
    }
    *(float4*)&out_feat[((size_t)b * S_ + s) * DOUT_ + col * 4] = acc;
}

// ============================================================================
extern "C" void kernel_launch(void* const* d_in, const int* in_sizes, int n_in,
                              void* d_out, int out_size)
{
    const float* coords   = (const float*)d_in[0];
    const float* features = (const float*)d_in[1];
    const float* W        = (const float*)d_in[2];
    const float* bias     = (const float*)d_in[3];
    const float* gamma    = (const float*)d_in[4];
    const float* beta     = (const float*)d_in[5];
    const float* rmean    = (const float*)d_in[6];
    const float* rvar     = (const float*)d_in[7];

    float* out        = (float*)d_out;
    float* out_coords = out;                       // [B, S, 3]
    float* out_feat   = out + (size_t)B_ * S_ * 3; // [B, S, 128]

    static bool attr_done = false;
    if (!attr_done) {
        cudaFuncSetAttribute(fps_kernel, cudaFuncAttributeMaxDynamicSharedMemorySize,
                             N_ * (int)sizeof(float4));
        attr_done = true;
    }

    fps_kernel<<<B_, 1024, N_ * sizeof(float4)>>>(coords, out_coords);
    mlp_kernel<<<(B_ * N_) / 32, 256>>>(features, W, bias, gamma, beta, rmean, rvar);
    knn_kernel<<<dim3(S_ / 128, B_), 128>>>(coords);
    pool_kernel<<<dim3(S_ / 8, B_), 256>>>(out_feat);
}